// round 17
// baseline (speedup 1.0000x reference)
#include <cuda_runtime.h>
#include <math.h>
#include <stdint.h>

// ---------------- problem constants ----------------
#define BB    2
#define QQN   4
#define NH    32
#define NHK   8
#define HD    128
#define DMODEL 4096
#define KVLEN 4096
#define STOT  4100          // KVLEN + QQN
#define RSEL  410           // max(128, 4100 - int(4100*0.9))
#define NCTOT 6144          // 4096 (q) + 1024 (k) + 1024 (v)
#define PKC   32            // proj split-K chunks (chunk = 128)
#define OKC   64            // out-proj split-K chunks (chunk = 64)

// ---------------- device scratch ----------------
__device__ float g_invf[64];
__device__ float g_cos[STOT * 64];
__device__ float g_sin[STOT * 64];
__device__ float g_pp[PKC][8][NCTOT];          // projection partials
__device__ float g_qrope[BB * NH * QQN * HD];  // roped queries
__device__ float g_knew[BB * NHK * QQN * HD];  // roped new keys
__device__ float g_vnew[BB * NHK * QQN * HD];  // new values (raw)
__device__ float g_scores[(size_t)BB * NH * QQN * STOT];
__device__ float g_attn[BB * QQN * DMODEL];    // [b][q][h*HD+d]
__device__ float g_op[OKC][8][DMODEL];         // out-proj partials

// ---------------- 1) rope tables (numerics: identical fp32 chain) -------------
__global__ void invf_kernel() {
    int j = threadIdx.x;
    if (j < 64) {
        float expo = (float)(2 * j) / 128.0f;   // exact
        g_invf[j] = 1.0f / powf(10000.0f, expo);
    }
}

__global__ void rope_table_kernel() {
    int i = blockIdx.x * blockDim.x + threadIdx.x;
    if (i >= STOT * 64) return;
    int p = i >> 6;
    float invf = g_invf[i & 63];
    float ang = (float)p * invf;
    g_cos[i] = cosf(ang);
    g_sin[i] = sinf(ang);
}

// ---------------- 2) fused QKV projection (split-K partials) ----------------
__global__ void __launch_bounds__(128) proj_kernel(
        const float* __restrict__ hidden,
        const float* __restrict__ Wq,
        const float* __restrict__ Wk,
        const float* __restrict__ Wv) {
    __shared__ float hs[8][128];
    int tile = blockIdx.x;   // 0..11
    int kc   = blockIdx.y;   // 0..31
    int tid  = threadIdx.x;  // 0..127
    int k0   = kc * 128;

    for (int i = tid; i < 256; i += 128) {
        int f = i * 4;
        int m = f >> 7;
        int d = f & 127;
        *(float4*)&hs[m][d] = *(const float4*)&hidden[m * DMODEL + k0 + d];
    }
    __syncthreads();

    const float* W;
    int ld, colbase;
    if (tile < 8)       { W = Wq; ld = 4096; colbase = tile * 512; }
    else if (tile < 10) { W = Wk; ld = 1024; colbase = tile * 512 - 4096; }
    else                { W = Wv; ld = 1024; colbase = tile * 512 - 5120; }

    int wcol = colbase + tid * 4;
    const float* Wp = W + (size_t)k0 * ld + wcol;

    float4 a[8];
    #pragma unroll
    for (int m = 0; m < 8; m++) { a[m].x = 0.f; a[m].y = 0.f; a[m].z = 0.f; a[m].w = 0.f; }

    #pragma unroll 8
    for (int d = 0; d < 128; d++) {
        float4 wv = *(const float4*)(Wp + (size_t)d * ld);
        #pragma unroll
        for (int m = 0; m < 8; m++) {
            float h = hs[m][d];
            a[m].x = fmaf(h, wv.x, a[m].x);
            a[m].y = fmaf(h, wv.y, a[m].y);
            a[m].z = fmaf(h, wv.z, a[m].z);
            a[m].w = fmaf(h, wv.w, a[m].w);
        }
    }

    int gc = tile * 512 + tid * 4;
    #pragma unroll
    for (int m = 0; m < 8; m++)
        *(float4*)&g_pp[kc][m][gc] = a[m];
}

// ---------------- 3) reduce partials + rope q / new-k (pair-fused, float4) ---
// Rope-pair threads read each partial ONCE (lower+upper quad) and write both
// outputs; v threads do a plain float4 reduce. 7168 threads total.
__global__ void __launch_bounds__(256) proj_reduce_kernel() {
    int idx = blockIdx.x * blockDim.x + threadIdx.x;

    if (idx < 5120) {
        // q/k_new rope pairs: m (0..7), row r (0..39), quad qd (0..15)
        int m  = idx / 640;            // 8 m-values x 640 work items
        int rq = idx - m * 640;
        int r  = rq >> 4;              // 0..39 (row = 128 dims)
        int qd = rq & 15;              // quad within lower half
        int d0 = qd * 4;
        int c_lo = r * 128 + d0;
        int c_hi = c_lo + 64;

        float4 slo = make_float4(0.f, 0.f, 0.f, 0.f);
        float4 shi = make_float4(0.f, 0.f, 0.f, 0.f);
        #pragma unroll
        for (int k = 0; k < PKC; k++) {
            float4 a = *(const float4*)&g_pp[k][m][c_lo];
            float4 bq = *(const float4*)&g_pp[k][m][c_hi];
            slo.x += a.x; slo.y += a.y; slo.z += a.z; slo.w += a.w;
            shi.x += bq.x; shi.y += bq.y; shi.z += bq.z; shi.w += bq.w;
        }

        int b  = m >> 2;
        int qq = m & 3;
        int p  = KVLEN + qq;
        float4 ct = *(const float4*)&g_cos[p * 64 + d0];
        float4 st = *(const float4*)&g_sin[p * 64 + d0];

        float4 rlo, rhi;
        rlo.x = slo.x * ct.x + (-shi.x) * st.x;
        rlo.y = slo.y * ct.y + (-shi.y) * st.y;
        rlo.z = slo.z * ct.z + (-shi.z) * st.z;
        rlo.w = slo.w * ct.w + (-shi.w) * st.w;
        rhi.x = shi.x * ct.x + slo.x * st.x;
        rhi.y = shi.y * ct.y + slo.y * st.y;
        rhi.z = shi.z * ct.z + slo.z * st.z;
        rhi.w = shi.w * ct.w + slo.w * st.w;

        float* dst;
        if (r < 32) {  // q head r
            dst = &g_qrope[(((b * NH + r) * QQN) + qq) * HD];
        } else {       // k_new head r-32
            dst = &g_knew[(((b * NHK + (r - 32)) * QQN) + qq) * HD];
        }
        *(float4*)(dst + d0) = rlo;
        *(float4*)(dst + d0 + 64) = rhi;
    } else if (idx < 5120 + 2048) {
        // v_new: m (0..7), quad of 1024 dims
        int i2 = idx - 5120;
        int m  = i2 >> 8;
        int c4 = 5120 + (i2 & 255) * 4;
        float4 s = make_float4(0.f, 0.f, 0.f, 0.f);
        #pragma unroll
        for (int k = 0; k < PKC; k++) {
            float4 v = *(const float4*)&g_pp[k][m][c4];
            s.x += v.x; s.y += v.y; s.z += v.z; s.w += v.w;
        }
        int b  = m >> 2;
        int qq = m & 3;
        int d0 = c4 & 127;
        int hk = (c4 - 5120) >> 7;
        *(float4*)&g_vnew[(((b * NHK + hk) * QQN) + qq) * HD + d0] = s;
    }
}

// ---------------- 4) draft scores -------------------------------------------
// 16 lanes/key, 2 keys/warp. Each lane owns dims [4sl..4sl+3] AND [4sl+64..+67]
// (the rotation PAIR) -> zero partner shuffles, one cos/sin float4 serves both
// halves. Reduction: xor4/xor8 on 4 accs, pick acc[(l>>2)&3], xor1/xor2.
__device__ __forceinline__ void reduce_store_2key(
    float acc0, float acc1, float acc2, float acc3,
    int l, float* __restrict__ sb, int jbase)
{
    acc0 += __shfl_xor_sync(0xffffffffu, acc0, 4);
    acc1 += __shfl_xor_sync(0xffffffffu, acc1, 4);
    acc2 += __shfl_xor_sync(0xffffffffu, acc2, 4);
    acc3 += __shfl_xor_sync(0xffffffffu, acc3, 4);
    acc0 += __shfl_xor_sync(0xffffffffu, acc0, 8);
    acc1 += __shfl_xor_sync(0xffffffffu, acc1, 8);
    acc2 += __shfl_xor_sync(0xffffffffu, acc2, 8);
    acc3 += __shfl_xor_sync(0xffffffffu, acc3, 8);
    int qi = (l >> 2) & 3;
    float w = (qi == 0) ? acc0 : (qi == 1) ? acc1 : (qi == 2) ? acc2 : acc3;
    w += __shfl_xor_sync(0xffffffffu, w, 1);
    w += __shfl_xor_sync(0xffffffffu, w, 2);
    if ((l & 3) == 0)
        sb[(size_t)qi * STOT + jbase + (l >> 4)] = w;
}

__device__ __forceinline__ float dot8(float4 a0, float4 a1, float4 b0, float4 b1) {
    float s = a0.x * b0.x;
    s = fmaf(a0.y, b0.y, s);
    s = fmaf(a0.z, b0.z, s);
    s = fmaf(a0.w, b0.w, s);
    s = fmaf(a1.x, b1.x, s);
    s = fmaf(a1.y, b1.y, s);
    s = fmaf(a1.z, b1.z, s);
    s = fmaf(a1.w, b1.w, s);
    return s;
}

__global__ void __launch_bounds__(256) score_kernel(const float* __restrict__ kcache) {
    int bh = blockIdx.x;              // 0..63
    int b  = bh >> 5;
    int h  = bh & 31;
    int ks = blockIdx.y;              // 0..7 -> 512 cache keys each
    int tid = threadIdx.x;
    int w = tid >> 5;
    int l = tid & 31;
    int g  = l >> 4;                  // which of the warp's 2 keys
    int sl = l & 15;                  // sublane within key group
    int d0 = sl * 4;                  // lane owns dims [d0..d0+3] + [d0+64..d0+67]

    // q: 4 queries x (lower quad + upper quad) in registers
    const float* qb = g_qrope + (size_t)bh * QQN * HD;
    float4 qA[4], qB[4];
    #pragma unroll
    for (int qi = 0; qi < 4; qi++) {
        qA[qi] = *(const float4*)(qb + qi * HD + d0);
        qB[qi] = *(const float4*)(qb + qi * HD + d0 + 64);
    }

    const float* kb = kcache + (size_t)bh * KVLEN * HD;
    float* sb = g_scores + (size_t)bh * QQN * STOT;

    int j0 = ks * 512;
    int jbase = j0 + 2 * w;           // key pair {jbase, jbase+1}, stride 16

    // 1-deep prefetch pipeline (4 float4)
    const float* kp = kb + (size_t)(jbase + g) * HD + d0;
    float4 kA = *(const float4*)kp;        // dims d0..d0+3
    float4 kB = *(const float4*)(kp + 64); // dims d0+64..d0+67
    float4 c4 = *(const float4*)&g_cos[(jbase + g) * 64 + d0];
    float4 s4 = *(const float4*)&g_sin[(jbase + g) * 64 + d0];

    #pragma unroll 2
    for (int t = 0; t < 32; t++) {
        int jn = jbase + 16;
        float4 kA2 = kA, kB2 = kB, c42 = c4, s42 = s4;
        if (t < 31) {
            const float* kp2 = kb + (size_t)(jn + g) * HD + d0;
            kA2 = *(const float4*)kp2;
            kB2 = *(const float4*)(kp2 + 64);
            c42 = *(const float4*)&g_cos[(jn + g) * 64 + d0];
            s42 = *(const float4*)&g_sin[(jn + g) * 64 + d0];
        }

        // RoPE: both rotation halves in-register (no shuffles)
        float4 krA, krB;
        krA.x = kA.x * c4.x + (-kB.x) * s4.x;
        krA.y = kA.y * c4.y + (-kB.y) * s4.y;
        krA.z = kA.z * c4.z + (-kB.z) * s4.z;
        krA.w = kA.w * c4.w + (-kB.w) * s4.w;
        krB.x = kB.x * c4.x + kA.x * s4.x;
        krB.y = kB.y * c4.y + kA.y * s4.y;
        krB.z = kB.z * c4.z + kA.z * s4.z;
        krB.w = kB.w * c4.w + kA.w * s4.w;

        float a0 = dot8(krA, krB, qA[0], qB[0]);
        float a1 = dot8(krA, krB, qA[1], qB[1]);
        float a2 = dot8(krA, krB, qA[2], qB[2]);
        float a3 = dot8(krA, krB, qA[3], qB[3]);
        reduce_store_2key(a0, a1, a2, a3, l, sb, jbase);

        kA = kA2; kB = kB2; c4 = c42; s4 = s42;
        jbase = jn;
    }

    // last split also scores the 4 freshly-projected (already roped) keys
    if (ks == 7 && w < 2) {
        int qq = 2 * w + g;               // 0..3
        int jj = KVLEN + 2 * w;           // pair base
        const float* krp = g_knew + (((b * NHK + (h >> 2)) * QQN) + qq) * HD;
        float4 krA = *(const float4*)(krp + d0);
        float4 krB = *(const float4*)(krp + d0 + 64);
        float a0 = dot8(krA, krB, qA[0], qB[0]);
        float a1 = dot8(krA, krB, qA[1], qB[1]);
        float a2 = dot8(krA, krB, qA[2], qB[2]);
        float a3 = dot8(krA, krB, qA[3], qB[3]);
        reduce_store_2key(a0, a1, a2, a3, l, sb, jj);
    }
}

// ---------------- 5) exact top-410 radix select + softmax + V gather --------
__device__ __forceinline__ unsigned fkey(float f) {
    unsigned u = __float_as_uint(f);
    return (u & 0x80000000u) ? ~u : (u | 0x80000000u);  // order-preserving
}

__global__ void __launch_bounds__(512) select_kernel(const float* __restrict__ vcache) {
    __shared__ float sc[STOT];
    __shared__ unsigned hist[256];
    __shared__ int   s_idx[512];
    __shared__ float s_w[512];
    __shared__ float red[512];
    __shared__ float acc4[4][HD];
    __shared__ int s_bin, s_rem, s_cnt;

    int blk = blockIdx.x;           // 0..255
    int qq = blk & 3;
    int h  = (blk >> 2) & 31;
    int b  = blk >> 7;
    int bh = b * NH + h;
    int tid = threadIdx.x;
    int lane = tid & 31;

    const float* srow = g_scores + ((size_t)bh * QQN + qq) * STOT;

    float lmax = -3.402823466e38f;
    for (int i = tid; i < STOT; i += 512) {
        float v = srow[i];
        sc[i] = v;
        lmax = fmaxf(lmax, v);
    }
    red[tid] = lmax;
    __syncthreads();
    for (int o = 256; o; o >>= 1) {
        if (tid < o) red[tid] = fmaxf(red[tid], red[tid + o]);
        __syncthreads();
    }
    float rmax = red[0];
    __syncthreads();

    // radix select the RSEL-th largest key (exact); warp-aggregated histogram
    unsigned prefix = 0;
    int remaining = RSEL;
    for (int shift = 24; shift >= 0; shift -= 8) {
        if (tid < 256) hist[tid] = 0;
        __syncthreads();
        unsigned pmask = (shift == 24) ? 0u : (0xFFFFFFFFu << (shift + 8));
        for (int i = tid; i < 4608; i += 512) {   // padded: all warps full
            unsigned k = (i < STOT) ? fkey(sc[i]) : 0u;
            bool ok = (i < STOT) && ((k & pmask) == prefix);
            unsigned act = __ballot_sync(0xffffffffu, ok);
            if (ok) {
                int bin = (int)((k >> shift) & 255u);
                unsigned peers = __match_any_sync(act, bin);
                if (lane == __ffs(peers) - 1)
                    atomicAdd(&hist[bin], (unsigned)__popc(peers));
            }
        }
        __syncthreads();
        // parallel inclusive suffix sum (Hillis-Steele) over 256 bins
        #pragma unroll
        for (int off = 1; off < 256; off <<= 1) {
            unsigned v = 0, ad = 0;
            if (tid < 256) {
                v = hist[tid];
                ad = (tid + off < 256) ? hist[tid + off] : 0u;
            }
            __syncthreads();
            if (tid < 256) hist[tid] = v + ad;
            __syncthreads();
        }
        if (tid < 256) {
            unsigned sfx = hist[tid];
            unsigned nxt = (tid < 255) ? hist[tid + 1] : 0u;
            if ((int)sfx >= remaining && (int)nxt < remaining) {
                s_bin = tid;
                s_rem = remaining - (int)nxt;
            }
        }
        __syncthreads();
        prefix |= ((unsigned)s_bin) << shift;
        remaining = s_rem;
        __syncthreads();
    }
    unsigned thr = prefix;

    if (tid == 0) s_cnt = 0;
    __syncthreads();
    const float inv_sqrt = 0.08838834764831845f;  // 1/sqrt(128)
    float lden = 0.f;
    for (int i = tid; i < 4608; i += 512) {
        bool sel = (i < STOT) && (fkey(sc[i]) >= thr);
        unsigned bal = __ballot_sync(0xffffffffu, sel);
        int nsel = __popc(bal);
        int base = 0;
        if (nsel) {
            int ldr = __ffs(bal) - 1;
            if (lane == ldr) base = atomicAdd(&s_cnt, nsel);
            base = __shfl_sync(0xffffffffu, base, ldr);
        }
        if (sel) {
            int pos = base + __popc(bal & ((1u << lane) - 1u));
            float wgt = expf((sc[i] - rmax) * inv_sqrt);
            lden += wgt;
            if (pos < 512) { s_idx[pos] = i; s_w[pos] = wgt; }
        }
    }
    red[tid] = lden;
    __syncthreads();
    for (int o = 256; o; o >>= 1) {
        if (tid < o) red[tid] += red[tid + o];
        __syncthreads();
    }
    float den = red[0];
    __syncthreads();
    int n = s_cnt < 512 ? s_cnt : 512;

    // gather V (coalesced 512B rows), FOUR key-quarters in parallel, ILP 4
    int quarter = tid >> 7;         // 0..3
    int d = tid & 127;
    const float* vb = vcache + (size_t)bh * KVLEN * HD;
    const float* vn = g_vnew + (((b * NHK + (h >> 2)) * QQN)) * HD;
    float a = 0.f;
    #pragma unroll 4
    for (int i = quarter; i < n; i += 4) {
        int j = s_idx[i];
        float wv = s_w[i];
        float v = (j < KVLEN) ? vb[(size_t)j * HD + d]
                              : vn[(j - KVLEN) * HD + d];
        a = fmaf(wv, v, a);
    }
    acc4[quarter][d] = a;
    __syncthreads();
    if (tid < HD) {
        float o = ((acc4[0][tid] + acc4[1][tid]) + (acc4[2][tid] + acc4[3][tid])) / den;
        g_attn[((size_t)(b * QQN + qq)) * DMODEL + h * HD + tid] = o;
    }
}

// ---------------- 6) output projection (split-K partials) ----------------
__global__ void __launch_bounds__(128) oproj_kernel(const float* __restrict__ Wo) {
    __shared__ float hs[8][64];
    int tile = blockIdx.x;   // 0..7 (512 cols each)
    int kc   = blockIdx.y;   // 0..63 (chunk 64)
    int tid  = threadIdx.x;  // 0..127
    int k0   = kc * 64;

    {
        int f = tid * 4;
        int m = f >> 6;
        int d = f & 63;
        *(float4*)&hs[m][d] = *(const float4*)&g_attn[m * DMODEL + k0 + d];
    }
    __syncthreads();

    int col = tile * 512 + tid * 4;
    const float* Wp = Wo + (size_t)k0 * DMODEL + col;

    float4 a[8];
    #pragma unroll
    for (int m = 0; m < 8; m++) { a[m].x = 0.f; a[m].y = 0.f; a[m].z = 0.f; a[m].w = 0.f; }

    #pragma unroll 8
    for (int dd = 0; dd < 64; dd++) {
        float4 wv = *(const float4*)(Wp + (size_t)dd * DMODEL);
        #pragma unroll
        for (int m = 0; m < 8; m++) {
            float h = hs[m][dd];
            a[m].x = fmaf(h, wv.x, a[m].x);
            a[m].y = fmaf(h, wv.y, a[m].y);
            a[m].z = fmaf(h, wv.z, a[m].z);
            a[m].w = fmaf(h, wv.w, a[m].w);
        }
    }
    #pragma unroll
    for (int m = 0; m < 8; m++)
        *(float4*)&g_op[kc][m][col] = a[m];
}

__global__ void __launch_bounds__(256) oreduce_kernel(float* __restrict__ out) {
    int idx = blockIdx.x * blockDim.x + threadIdx.x;   // 8192 threads
    if (idx >= 8 * (DMODEL / 4)) return;
    int c4 = (idx & 1023) * 4;
    int m  = idx >> 10;
    float4 s = make_float4(0.f, 0.f, 0.f, 0.f);
    #pragma unroll
    for (int k = 0; k < OKC; k++) {
        float4 v = *(const float4*)&g_op[k][m][c4];
        s.x += v.x; s.y += v.y; s.z += v.z; s.w += v.w;
    }
    *(float4*)&out[(size_t)m * DMODEL + c4] = s;
}

// ---------------- launch ----------------
extern "C" void kernel_launch(void* const* d_in, const int* in_sizes, int n_in,
                              void* d_out, int out_size) {
    const float* hidden = (const float*)d_in[0];
    const float* kcache = (const float*)d_in[1];
    const float* vcache = (const float*)d_in[2];
    const float* Wq     = (const float*)d_in[3];
    const float* Wk     = (const float*)d_in[4];
    const float* Wv     = (const float*)d_in[5];
    const float* Wo     = (const float*)d_in[6];
    float* out = (float*)d_out;

    invf_kernel<<<1, 64>>>();
    rope_table_kernel<<<(STOT * 64 + 255) / 256, 256>>>();
    proj_kernel<<<dim3(12, 32), 128>>>(hidden, Wq, Wk, Wv);
    proj_reduce_kernel<<<28, 256>>>();
    score_kernel<<<dim3(64, 8), 256>>>(kcache);
    select_kernel<<<256, 512>>>(vcache);
    oproj_kernel<<<dim3(8, 64), 128>>>(Wo);
    oreduce_kernel<<<32, 256>>>(out);
}